// round 11
// baseline (speedup 1.0000x reference)
#include <cuda_runtime.h>
#include <cuda_bf16.h>
#include <math.h>
#include <stdint.h>

#define B_  32
#define T_  512
#define D_  1024
#define H_  16
#define HD_ 64
#define M_  (B_ * T_)      // 16384
#define N3  (3 * D_)       // 3072

#define NEG_INF __int_as_float(0xff800000)

typedef __nv_bfloat16 bf16;

// ---------------- device scratch ----------------
__device__ bf16 g_xh[M_ * D_],   g_xl[M_ * D_];
__device__ bf16 g_kqvh[M_ * N3], g_kqvl[M_ * N3];
__device__ bf16 g_ah[M_ * D_],   g_al[M_ * D_];
__device__ bf16 g_wih[D_ * D_],  g_wil[D_ * D_];    // Wi [K][N] row-major
__device__ bf16 g_wkh[D_ * N3],  g_wkl[D_ * N3];    // repacked Wkqv [K][N]
__device__ bf16 g_wph[D_ * N3],  g_wpl[D_ * N3];    // fused W' = Wi@Wkqv
__device__ bf16 g_woh[D_ * D_],  g_wol[D_ * D_];    // Wo [K][N]
__device__ float g_bkqv[N3];
__device__ float g_bfused[N3];
__device__ float g_zero[N3];

__device__ __forceinline__ void split1(float v, bf16& h, bf16& l) {
    h = __float2bfloat16_rn(v);
    l = __float2bfloat16_rn(v - __bfloat162float(h));
}

// ---------------- fp32 -> hi/lo bf16 split ----------------
__global__ void split_kernel(const float* __restrict__ src, bf16* __restrict__ dh,
                             bf16* __restrict__ dl, int n) {
    int i = (blockIdx.x * blockDim.x + threadIdx.x) * 4;
    if (i >= n) return;
    float4 v = *(const float4*)(src + i);
    bf16 h0, l0, h1, l1, h2, l2, h3, l3;
    split1(v.x, h0, l0); split1(v.y, h1, l1);
    split1(v.z, h2, l2); split1(v.w, h3, l3);
    uint32_t hh0 = (uint32_t)__bfloat16_as_ushort(h0) | ((uint32_t)__bfloat16_as_ushort(h1) << 16);
    uint32_t hh1 = (uint32_t)__bfloat16_as_ushort(h2) | ((uint32_t)__bfloat16_as_ushort(h3) << 16);
    uint32_t ll0 = (uint32_t)__bfloat16_as_ushort(l0) | ((uint32_t)__bfloat16_as_ushort(l1) << 16);
    uint32_t ll1 = (uint32_t)__bfloat16_as_ushort(l2) | ((uint32_t)__bfloat16_as_ushort(l3) << 16);
    *(uint2*)(dh + i) = make_uint2(hh0, hh1);
    *(uint2*)(dl + i) = make_uint2(ll0, ll1);
}

// ---------------- weight repack + split ----------------
__global__ void repack_split_kernel(const float* __restrict__ Wk, const float* __restrict__ Wq,
                                    const float* __restrict__ Wv, const float* __restrict__ bk,
                                    const float* __restrict__ bq, const float* __restrict__ bv) {
    int idx = blockIdx.x * blockDim.x + threadIdx.x;
    const int per = H_ * D_ * HD_;
    if (idx < 3 * per) {
        int w  = idx / per;
        int r  = idx % per;
        int h  = r / (D_ * HD_);
        int r2 = r % (D_ * HD_);
        int d  = r2 / HD_;
        int e  = r2 % HD_;
        const float* src = (w == 0) ? Wk : ((w == 1) ? Wq : Wv);
        float v = src[h * D_ * HD_ + d * HD_ + e];
        bf16 hh, ll;
        split1(v, hh, ll);
        int o = d * N3 + w * D_ + h * HD_ + e;
        g_wkh[o] = hh;
        g_wkl[o] = ll;
    }
    if (idx < N3) {
        int w = idx / D_;
        int c = idx % D_;
        const float* bsrc = (w == 0) ? bk : ((w == 1) ? bq : bv);
        g_bkqv[idx] = bsrc[c];
    }
}

// ---------------- fused bias: b' = bi @ Wkqv + bkqv ----------------
__global__ void bias_fuse_kernel(const float* __restrict__ bi) {
    int n = blockIdx.x * blockDim.x + threadIdx.x;
    if (n >= N3) return;
    float acc = g_bkqv[n];
    for (int d = 0; d < D_; d++)
        acc += bi[d] * (__bfloat162float(g_wkh[d * N3 + n]) +
                        __bfloat162float(g_wkl[d * N3 + n]));
    g_bfused[n] = acc;
}

// ---------------- MMA / cp.async helpers ----------------
__device__ __forceinline__ void mma_bf16(float* d, const uint32_t* a, const uint32_t* b) {
    asm volatile("mma.sync.aligned.m16n8k16.row.col.f32.bf16.bf16.f32 "
                 "{%0,%1,%2,%3}, {%4,%5,%6,%7}, {%8,%9}, {%0,%1,%2,%3};"
                 : "+f"(d[0]), "+f"(d[1]), "+f"(d[2]), "+f"(d[3])
                 : "r"(a[0]), "r"(a[1]), "r"(a[2]), "r"(a[3]), "r"(b[0]), "r"(b[1]));
}

__device__ __forceinline__ void cp16(uint32_t dst, const void* src) {
    asm volatile("cp.async.cg.shared.global [%0], [%1], 16;" :: "r"(dst), "l"(src));
}
__device__ __forceinline__ void cp_commit() { asm volatile("cp.async.commit_group;"); }
template <int N> __device__ __forceinline__ void cp_wait() {
    asm volatile("cp.async.wait_group %0;" :: "n"(N));
}

// =======================================================================
// GEMM: block 128x256x32, warp 64x64, 8 warps, 1 CTA/SM, 3-stage cp.async.
// smem/stage: A 128rows x 128B (hi 4 | lo 4 chunks, XOR swizzle) = 16KB
//             B 32rows x 1024B (hi 32 | lo 32 chunks, XOR swizzle) = 32KB
// =======================================================================
#define GBM 128
#define GBN 256
#define GBK 32
#define SB_OFF 16384
#define STAGE 49152
#define NSTG 3
#define GEMM_SMEM (NSTG * STAGE)

__device__ __forceinline__ void g_ldmA(uint32_t* r, uint32_t sA, int m0, int kk, int hl, int lane) {
    int mrow  = m0 + (lane & 7) + ((lane >> 3) & 1) * 8;
    int chunk = ((kk >> 3) + (lane >> 4) + hl * 4) ^ (mrow & 7);
    uint32_t addr = sA + mrow * 128 + chunk * 16;
    asm volatile("ldmatrix.sync.aligned.m8n8.x4.shared.b16 {%0,%1,%2,%3}, [%4];"
                 : "=r"(r[0]), "=r"(r[1]), "=r"(r[2]), "=r"(r[3]) : "r"(addr));
}

__device__ __forceinline__ void g_ldmB(uint32_t* b0, uint32_t* b1, uint32_t sB,
                                       int kk, int nb, int hl, int lane) {
    int krow  = kk + (lane & 7) + ((lane >> 3) & 1) * 8;
    int nc    = nb + (lane >> 4) * 8;
    int chunk = (((nc >> 3) ^ (krow & 7)) + hl * 32);
    uint32_t addr = sB + krow * 1024 + chunk * 16;
    uint32_t r0, r1, r2, r3;
    asm volatile("ldmatrix.sync.aligned.m8n8.x4.trans.shared.b16 {%0,%1,%2,%3}, [%4];"
                 : "=r"(r0), "=r"(r1), "=r"(r2), "=r"(r3) : "r"(addr));
    b0[0] = r0; b0[1] = r1; b1[0] = r2; b1[1] = r3;
}

// OM: 0 = fp32 C, 1 = hi/lo bf16 C
template <int OM>
__global__ void __launch_bounds__(256, 1)
gemm_pre(int M, int N, int K,
         const bf16* __restrict__ Ah, const bf16* __restrict__ Al,
         const bf16* __restrict__ Bh, const bf16* __restrict__ Bl,
         const float* __restrict__ bias, float* __restrict__ C,
         bf16* __restrict__ Ch, bf16* __restrict__ Cl) {
    extern __shared__ char sm[];
    const int tid = threadIdx.x, lane = tid & 31, wid = tid >> 5;
    const int bm = blockIdx.y, bn = blockIdx.x;
    const int warp_m = wid >> 2, warp_n = wid & 3;   // 2 x 4 warps -> 64x64 tiles
    uint32_t sbase = (uint32_t)__cvta_generic_to_shared(sm);

    // fill mappings
    const int aRow = tid >> 1, aHL = tid & 1;                 // A: 128 rows x {hi,lo}
    const int bKr  = tid >> 3, bPiece = tid & 7;              // B: 32 rows x 8 pieces
    const int bHL  = bPiece >> 2, bQ = bPiece & 3;            // piece -> hi/lo + quarter

    const bf16* Asrc = (aHL ? Al : Ah) + (size_t)(bm * GBM + aRow) * K;
    const bf16* Bsrc = (bHL ? Bl : Bh) + (size_t)bKr * N + bn * GBN;

    auto fill = [&](int buf, int kt) {
        uint32_t sA = sbase + buf * STAGE;
        uint32_t sB = sA + SB_OFF;
        const bf16* a = Asrc + kt * GBK;
        #pragma unroll
        for (int j = 0; j < 4; j++) {
            int chunk = ((aHL * 4 + j) ^ (aRow & 7));
            cp16(sA + aRow * 128 + chunk * 16, a + j * 8);
        }
        const bf16* b = Bsrc + (size_t)kt * GBK * N;
        #pragma unroll
        for (int i = 0; i < 8; i++) {
            int c0 = bQ * 8 + i;                               // 0..31
            int chunk = (c0 ^ (bKr & 7)) + bHL * 32;
            cp16(sB + bKr * 1024 + chunk * 16, b + c0 * 8);
        }
        cp_commit();
    };

    float acc[4][8][4] = {};
    const int NT = K / GBK;

    fill(0, 0);
    if (NT > 1) fill(1, 1);

    for (int kt = 0; kt < NT; kt++) {
        const int cur = kt % NSTG;
        if (kt + 2 < NT) { fill((kt + 2) % NSTG, kt + 2); cp_wait<2>(); }
        else if (kt + 1 < NT) { cp_wait<1>(); }
        else { cp_wait<0>(); }
        __syncthreads();

        uint32_t sA = sbase + cur * STAGE;
        uint32_t sB = sA + SB_OFF;

        #pragma unroll
        for (int kk = 0; kk < GBK; kk += 16) {
            uint32_t bh[8][2], bl[8][2];
            #pragma unroll
            for (int q = 0; q < 4; q++) {
                g_ldmB(bh[2 * q], bh[2 * q + 1], sB, kk, warp_n * 64 + q * 16, 0, lane);
            }
            #pragma unroll
            for (int q = 0; q < 4; q++) {
                g_ldmB(bl[2 * q], bl[2 * q + 1], sB, kk, warp_n * 64 + q * 16, 1, lane);
            }
            #pragma unroll
            for (int mt = 0; mt < 4; mt++) {
                uint32_t ah[4], al[4];
                g_ldmA(ah, sA, warp_m * 64 + mt * 16, kk, 0, lane);
                g_ldmA(al, sA, warp_m * 64 + mt * 16, kk, 1, lane);
                #pragma unroll
                for (int nt = 0; nt < 8; nt++) mma_bf16(acc[mt][nt], ah, bh[nt]);
                #pragma unroll
                for (int nt = 0; nt < 8; nt++) mma_bf16(acc[mt][nt], al, bh[nt]);
                #pragma unroll
                for (int nt = 0; nt < 8; nt++) mma_bf16(acc[mt][nt], ah, bl[nt]);
            }
        }
        __syncthreads();
    }

    #pragma unroll
    for (int mt = 0; mt < 4; mt++) {
        int r0 = bm * GBM + warp_m * 64 + mt * 16 + (lane >> 2);
        #pragma unroll
        for (int nt = 0; nt < 8; nt++) {
            int c = bn * GBN + warp_n * 64 + nt * 8 + (lane & 3) * 2;
            float2 b2 = *(const float2*)(bias + c);
            float v00 = acc[mt][nt][0] + b2.x, v01 = acc[mt][nt][1] + b2.y;
            float v10 = acc[mt][nt][2] + b2.x, v11 = acc[mt][nt][3] + b2.y;
            if (OM == 0) {
                *(float2*)(C + (size_t)r0 * N + c)       = make_float2(v00, v01);
                *(float2*)(C + (size_t)(r0 + 8) * N + c) = make_float2(v10, v11);
            } else {
                bf16 h0, l0, h1, l1;
                split1(v00, h0, l0); split1(v01, h1, l1);
                *(uint32_t*)(Ch + (size_t)r0 * N + c) =
                    (uint32_t)__bfloat16_as_ushort(h0) | ((uint32_t)__bfloat16_as_ushort(h1) << 16);
                *(uint32_t*)(Cl + (size_t)r0 * N + c) =
                    (uint32_t)__bfloat16_as_ushort(l0) | ((uint32_t)__bfloat16_as_ushort(l1) << 16);
                split1(v10, h0, l0); split1(v11, h1, l1);
                *(uint32_t*)(Ch + (size_t)(r0 + 8) * N + c) =
                    (uint32_t)__bfloat16_as_ushort(h0) | ((uint32_t)__bfloat16_as_ushort(h1) << 16);
                *(uint32_t*)(Cl + (size_t)(r0 + 8) * N + c) =
                    (uint32_t)__bfloat16_as_ushort(l0) | ((uint32_t)__bfloat16_as_ushort(l1) << 16);
            }
        }
    }
}

// =======================================================================
// Tensor-core flash attention, 128-row t-tiles (unchanged from R9)
// =======================================================================
#define ATT_K 16384
#define ATT_Q 8192
#define ATT_SMEM (2 * ATT_K + 4 * ATT_Q)

__device__ __forceinline__ void ldmKA(uint32_t* r, uint32_t base, int m0, int kk, int lane) {
    int mrow  = m0 + (lane & 7) + ((lane >> 3) & 1) * 8;
    int chunk = ((kk >> 3) + (lane >> 4)) ^ (mrow & 7);
    uint32_t addr = base + mrow * 128 + chunk * 16;
    asm volatile("ldmatrix.sync.aligned.m8n8.x4.shared.b16 {%0,%1,%2,%3}, [%4];"
                 : "=r"(r[0]), "=r"(r[1]), "=r"(r[2]), "=r"(r[3]) : "r"(addr));
}

__device__ __forceinline__ void ldmQB(uint32_t* t0, uint32_t* t1, uint32_t base,
                                      int n0, int kk, int lane) {
    int g     = lane >> 3;
    int nrow  = n0 + (lane & 7) + (g >> 1) * 8;
    int chunk = ((kk >> 3) + (g & 1)) ^ (nrow & 7);
    uint32_t addr = base + nrow * 128 + chunk * 16;
    uint32_t r0, r1, r2, r3;
    asm volatile("ldmatrix.sync.aligned.m8n8.x4.shared.b16 {%0,%1,%2,%3}, [%4];"
                 : "=r"(r0), "=r"(r1), "=r"(r2), "=r"(r3) : "r"(addr));
    t0[0] = r0; t0[1] = r1; t1[0] = r2; t1[1] = r3;
}

__device__ __forceinline__ void ldmVB(uint32_t* t0, uint32_t* t1, uint32_t base,
                                      int kk, int nb, int lane) {
    int krow  = kk + (lane & 7) + ((lane >> 3) & 1) * 8;
    int nc    = nb + (lane >> 4) * 8;
    int chunk = (nc >> 3) ^ (krow & 7);
    uint32_t addr = base + krow * 128 + chunk * 16;
    uint32_t r0, r1, r2, r3;
    asm volatile("ldmatrix.sync.aligned.m8n8.x4.trans.shared.b16 {%0,%1,%2,%3}, [%4];"
                 : "=r"(r0), "=r"(r1), "=r"(r2), "=r"(r3) : "r"(addr));
    t0[0] = r0; t0[1] = r1; t1[0] = r2; t1[1] = r3;
}

__device__ __forceinline__ void copy_half_row(const bf16* __restrict__ src,
                                              char* dst_base, int row, int half) {
    #pragma unroll
    for (int j = 0; j < 4; j++) {
        int chunk = (half * 4 + j) ^ (row & 7);
        *(uint4*)(dst_base + row * 128 + chunk * 16) = *(const uint4*)(src + j * 8);
    }
}

__global__ void __launch_bounds__(256)
attn_tc(const bf16* __restrict__ kqvh, const bf16* __restrict__ kqvl,
        bf16* __restrict__ outh, bf16* __restrict__ outl) {
    extern __shared__ __align__(16) char smem[];
    char* p_kh = smem;
    char* p_kl = smem + ATT_K;
    char* p_qh = smem + 2 * ATT_K;
    char* p_ql = p_qh + ATT_Q;
    char* p_vh = p_ql + ATT_Q;
    char* p_vl = p_vh + ATT_Q;

    const int tid = threadIdx.x, lane = tid & 31, w = tid >> 5;
    const int tchunk = blockIdx.x, h = blockIdx.y, b = blockIdx.z;
    const int tbase = tchunk * 128;

    uint32_t sb = (uint32_t)__cvta_generic_to_shared(smem);
    uint32_t s_kh = sb,             s_kl = sb + ATT_K;
    uint32_t s_qh = sb + 2 * ATT_K, s_ql = s_qh + ATT_Q;
    uint32_t s_vh = s_ql + ATT_Q,   s_vl = s_vh + ATT_Q;

    {
        int row = tid >> 1, half = tid & 1;
        size_t off = (size_t)(b * T_ + tbase + row) * N3 + h * HD_ + half * 32;
        copy_half_row(kqvh + off, p_kh, row, half);
        copy_half_row(kqvl + off, p_kl, row, half);
    }
    __syncthreads();

    uint32_t kh[4][4], kl[4][4];
    #pragma unroll
    for (int ks = 0; ks < 4; ks++) {
        ldmKA(kh[ks], s_kh, w * 16, ks * 16, lane);
        ldmKA(kl[ks], s_kl, w * 16, ks * 16, lane);
    }

    float O[8][4];
    #pragma unroll
    for (int nt = 0; nt < 8; nt++)
        #pragma unroll
        for (int j = 0; j < 4; j++) O[nt][j] = 0.f;
    float m0 = NEG_INF, m1 = NEG_INF, l0 = 0.f, l1 = 0.f;

    const int qrow = tid >> 2, qq = tid & 3;
    const int cmax = 2 * tchunk + 1;

    for (int c = 0; c <= cmax; c++) {
        __syncthreads();
        {
            size_t off = (size_t)(b * T_ + c * 64 + qrow) * N3 + D_ + h * HD_;
            #pragma unroll
            for (int jj = 0; jj < 2; jj++) {
                int j = qq * 2 + jj;
                int chunk = j ^ (qrow & 7);
                int doff = qrow * 128 + chunk * 16;
                *(uint4*)(p_qh + doff) = *(const uint4*)(kqvh + off + j * 8);
                *(uint4*)(p_ql + doff) = *(const uint4*)(kqvl + off + j * 8);
                *(uint4*)(p_vh + doff) = *(const uint4*)(kqvh + off + D_ + j * 8);
                *(uint4*)(p_vl + doff) = *(const uint4*)(kqvl + off + D_ + j * 8);
            }
        }
        __syncthreads();

        if (c * 64 > tbase + w * 16 + 15) continue;

        float sa[8][4];
        #pragma unroll
        for (int nt = 0; nt < 8; nt++)
            #pragma unroll
            for (int j = 0; j < 4; j++) sa[nt][j] = 0.f;

        #pragma unroll
        for (int ks = 0; ks < 4; ks++) {
            uint32_t bq[8][2];
            #pragma unroll
            for (int np = 0; np < 4; np++)
                ldmQB(bq[2 * np], bq[2 * np + 1], s_qh, np * 16, ks * 16, lane);
            #pragma unroll
            for (int nt = 0; nt < 8; nt++) mma_bf16(sa[nt], kh[ks], bq[nt]);
            #pragma unroll
            for (int nt = 0; nt < 8; nt++) mma_bf16(sa[nt], kl[ks], bq[nt]);
            #pragma unroll
            for (int np = 0; np < 4; np++)
                ldmQB(bq[2 * np], bq[2 * np + 1], s_ql, np * 16, ks * 16, lane);
            #pragma unroll
            for (int nt = 0; nt < 8; nt++) mma_bf16(sa[nt], kh[ks], bq[nt]);
        }

        if (c * 64 + 63 > tbase + w * 16) {
            int rg = tbase + w * 16 + (lane >> 2);
            #pragma unroll
            for (int nt = 0; nt < 8; nt++) {
                int sg = c * 64 + nt * 8 + (lane & 3) * 2;
                if (sg + 0 > rg)     sa[nt][0] = NEG_INF;
                if (sg + 1 > rg)     sa[nt][1] = NEG_INF;
                if (sg + 0 > rg + 8) sa[nt][2] = NEG_INF;
                if (sg + 1 > rg + 8) sa[nt][3] = NEG_INF;
            }
        }

        float cm0 = NEG_INF, cm1 = NEG_INF;
        #pragma unroll
        for (int nt = 0; nt < 8; nt++) {
            cm0 = fmaxf(cm0, fmaxf(sa[nt][0], sa[nt][1]));
            cm1 = fmaxf(cm1, fmaxf(sa[nt][2], sa[nt][3]));
        }
        cm0 = fmaxf(cm0, __shfl_xor_sync(0xffffffffu, cm0, 1));
        cm0 = fmaxf(cm0, __shfl_xor_sync(0xffffffffu, cm0, 2));
        cm1 = fmaxf(cm1, __shfl_xor_sync(0xffffffffu, cm1, 1));
        cm1 = fmaxf(cm1, __shfl_xor_sync(0xffffffffu, cm1, 2));

        float mn0 = fmaxf(m0, cm0), mn1 = fmaxf(m1, cm1);
        float al0 = __expf(m0 - mn0), al1 = __expf(m1 - mn1);
        m0 = mn0; m1 = mn1;
        l0 *= al0; l1 *= al1;
        #pragma unroll
        for (int nt = 0; nt < 8; nt++) {
            O[nt][0] *= al0; O[nt][1] *= al0;
            O[nt][2] *= al1; O[nt][3] *= al1;
        }

        #pragma unroll
        for (int nt = 0; nt < 8; nt++) {
            sa[nt][0] = __expf(sa[nt][0] - m0);
            sa[nt][1] = __expf(sa[nt][1] - m0);
            sa[nt][2] = __expf(sa[nt][2] - m1);
            sa[nt][3] = __expf(sa[nt][3] - m1);
            l0 += sa[nt][0] + sa[nt][1];
            l1 += sa[nt][2] + sa[nt][3];
        }

        #pragma unroll
        for (int ks = 0; ks < 4; ks++) {
            uint32_t ah[4], al[4];
            #pragma unroll
            for (int q = 0; q < 2; q++) {
                float p0 = sa[2 * ks][2 * q],     p1 = sa[2 * ks][2 * q + 1];
                float p2 = sa[2 * ks + 1][2 * q], p3 = sa[2 * ks + 1][2 * q + 1];
                bf16 h0, e0, h1, e1, h2, e2, h3, e3;
                split1(p0, h0, e0); split1(p1, h1, e1);
                split1(p2, h2, e2); split1(p3, h3, e3);
                ah[q]     = (uint32_t)__bfloat16_as_ushort(h0) | ((uint32_t)__bfloat16_as_ushort(h1) << 16);
                ah[q + 2] = (uint32_t)__bfloat16_as_ushort(h2) | ((uint32_t)__bfloat16_as_ushort(h3) << 16);
                al[q]     = (uint32_t)__bfloat16_as_ushort(e0) | ((uint32_t)__bfloat16_as_ushort(e1) << 16);
                al[q + 2] = (uint32_t)__bfloat16_as_ushort(e2) | ((uint32_t)__bfloat16_as_ushort(e3) << 16);
            }
            uint32_t bv[8][2];
            #pragma unroll
            for (int np = 0; np < 4; np++)
                ldmVB(bv[2 * np], bv[2 * np + 1], s_vh, ks * 16, np * 16, lane);
            #pragma unroll
            for (int nt = 0; nt < 8; nt++) mma_bf16(O[nt], ah, bv[nt]);
            #pragma unroll
            for (int nt = 0; nt < 8; nt++) mma_bf16(O[nt], al, bv[nt]);
            #pragma unroll
            for (int np = 0; np < 4; np++)
                ldmVB(bv[2 * np], bv[2 * np + 1], s_vl, ks * 16, np * 16, lane);
            #pragma unroll
            for (int nt = 0; nt < 8; nt++) mma_bf16(O[nt], ah, bv[nt]);
        }
    }

    l0 += __shfl_xor_sync(0xffffffffu, l0, 1);
    l0 += __shfl_xor_sync(0xffffffffu, l0, 2);
    l1 += __shfl_xor_sync(0xffffffffu, l1, 1);
    l1 += __shfl_xor_sync(0xffffffffu, l1, 2);
    float inv0 = 1.f / l0, inv1 = 1.f / l1;

    int r0 = tbase + w * 16 + (lane >> 2);
    #pragma unroll
    for (int nt = 0; nt < 8; nt++) {
        int col = h * HD_ + nt * 8 + (lane & 3) * 2;
        float v00 = O[nt][0] * inv0, v01 = O[nt][1] * inv0;
        float v10 = O[nt][2] * inv1, v11 = O[nt][3] * inv1;
        bf16 h0, e0, h1, e1;
        split1(v00, h0, e0); split1(v01, h1, e1);
        *(uint32_t*)(outh + (size_t)(b * T_ + r0) * D_ + col) =
            (uint32_t)__bfloat16_as_ushort(h0) | ((uint32_t)__bfloat16_as_ushort(h1) << 16);
        *(uint32_t*)(outl + (size_t)(b * T_ + r0) * D_ + col) =
            (uint32_t)__bfloat16_as_ushort(e0) | ((uint32_t)__bfloat16_as_ushort(e1) << 16);
        split1(v10, h0, e0); split1(v11, h1, e1);
        *(uint32_t*)(outh + (size_t)(b * T_ + r0 + 8) * D_ + col) =
            (uint32_t)__bfloat16_as_ushort(h0) | ((uint32_t)__bfloat16_as_ushort(h1) << 16);
        *(uint32_t*)(outl + (size_t)(b * T_ + r0 + 8) * D_ + col) =
            (uint32_t)__bfloat16_as_ushort(e0) | ((uint32_t)__bfloat16_as_ushort(e1) << 16);
    }
}

// ---------------- launch ----------------
extern "C" void kernel_launch(void* const* d_in, const int* in_sizes, int n_in,
                              void* d_out, int out_size) {
    const float* x  = (const float*)d_in[0];
    const float* Wi = (const float*)d_in[1];
    const float* bi = (const float*)d_in[2];
    const float* Wk = (const float*)d_in[3];
    const float* bk = (const float*)d_in[4];
    const float* Wq = (const float*)d_in[5];
    const float* bq = (const float*)d_in[6];
    const float* Wv = (const float*)d_in[7];
    const float* bv = (const float*)d_in[8];
    const float* Wo = (const float*)d_in[9];
    const float* bo = (const float*)d_in[10];
    float* out = (float*)d_out;

    bf16 *p_xh, *p_xl, *p_kqvh, *p_kqvl, *p_ah, *p_al;
    bf16 *p_wih, *p_wil, *p_wkh, *p_wkl, *p_wph, *p_wpl, *p_woh, *p_wol;
    float *p_bfused, *p_zero;
    cudaGetSymbolAddress((void**)&p_xh, g_xh);     cudaGetSymbolAddress((void**)&p_xl, g_xl);
    cudaGetSymbolAddress((void**)&p_kqvh, g_kqvh); cudaGetSymbolAddress((void**)&p_kqvl, g_kqvl);
    cudaGetSymbolAddress((void**)&p_ah, g_ah);     cudaGetSymbolAddress((void**)&p_al, g_al);
    cudaGetSymbolAddress((void**)&p_wih, g_wih);   cudaGetSymbolAddress((void**)&p_wil, g_wil);
    cudaGetSymbolAddress((void**)&p_wkh, g_wkh);   cudaGetSymbolAddress((void**)&p_wkl, g_wkl);
    cudaGetSymbolAddress((void**)&p_wph, g_wph);   cudaGetSymbolAddress((void**)&p_wpl, g_wpl);
    cudaGetSymbolAddress((void**)&p_woh, g_woh);   cudaGetSymbolAddress((void**)&p_wol, g_wol);
    cudaGetSymbolAddress((void**)&p_bfused, g_bfused);
    cudaGetSymbolAddress((void**)&p_zero, g_zero);

    static bool attr_set = false;
    if (!attr_set) {
        cudaFuncSetAttribute(gemm_pre<0>, cudaFuncAttributeMaxDynamicSharedMemorySize, GEMM_SMEM);
        cudaFuncSetAttribute(gemm_pre<1>, cudaFuncAttributeMaxDynamicSharedMemorySize, GEMM_SMEM);
        cudaFuncSetAttribute(attn_tc,     cudaFuncAttributeMaxDynamicSharedMemorySize, ATT_SMEM);
        attr_set = true;
    }

    // splits / repack
    split_kernel<<<(M_ * D_ / 4 + 255) / 256, 256>>>(x,  p_xh,  p_xl,  M_ * D_);
    split_kernel<<<(D_ * D_ / 4 + 255) / 256, 256>>>(Wi, p_wih, p_wil, D_ * D_);
    split_kernel<<<(D_ * D_ / 4 + 255) / 256, 256>>>(Wo, p_woh, p_wol, D_ * D_);
    repack_split_kernel<<<(3 * H_ * D_ * HD_ + 255) / 256, 256>>>(Wk, Wq, Wv, bk, bq, bv);
    bias_fuse_kernel<<<(N3 + 255) / 256, 256>>>(bi);

    {   // W' = Wi @ Wkqv  -> hi/lo   [1024 x 3072]
        dim3 grid(N3 / GBN, D_ / GBM);
        gemm_pre<1><<<grid, 256, GEMM_SMEM>>>(D_, N3, D_, p_wih, p_wil, p_wkh, p_wkl,
                                              p_zero, nullptr, p_wph, p_wpl);
    }
    {   // kqv = x @ W' + b'  -> hi/lo   [16384 x 3072]
        dim3 grid(N3 / GBN, M_ / GBM);
        gemm_pre<1><<<grid, 256, GEMM_SMEM>>>(M_, N3, D_, p_xh, p_xl, p_wph, p_wpl,
                                              p_bfused, nullptr, p_kqvh, p_kqvl);
    }
    {   // attention -> hi/lo  (128-row t-tiles)
        dim3 grid(T_ / 128, H_, B_);
        attn_tc<<<grid, 256, ATT_SMEM>>>(p_kqvh, p_kqvl, p_ah, p_al);
    }
    {   // out = attn @ Wo + bo -> fp32
        dim3 grid(D_ / GBN, M_ / GBM);
        gemm_pre<0><<<grid, 256, GEMM_SMEM>>>(M_, D_, D_, p_ah, p_al, p_woh, p_wol,
                                              bo, out, nullptr, nullptr);
    }
}

// round 12
// speedup vs baseline: 1.8235x; 1.8235x over previous
#include <cuda_runtime.h>
#include <cuda_bf16.h>
#include <math.h>
#include <stdint.h>

#define B_  32
#define T_  512
#define D_  1024
#define H_  16
#define HD_ 64
#define M_  (B_ * T_)      // 16384
#define N3  (3 * D_)       // 3072

#define NEG_INF __int_as_float(0xff800000)

typedef __nv_bfloat16 bf16;

// ---------------- device scratch ----------------
__device__ bf16 g_xh[M_ * D_],   g_xl[M_ * D_];
__device__ bf16 g_kqvh[M_ * N3], g_kqvl[M_ * N3];
__device__ bf16 g_ah[M_ * D_],   g_al[M_ * D_];
__device__ bf16 g_wih[D_ * D_],  g_wil[D_ * D_];    // Wi [K][N] row-major
__device__ bf16 g_wkh[D_ * N3],  g_wkl[D_ * N3];    // repacked Wkqv [K][N]
__device__ bf16 g_wph[D_ * N3],  g_wpl[D_ * N3];    // fused W' = Wi@Wkqv
__device__ bf16 g_woh[D_ * D_],  g_wol[D_ * D_];    // Wo [K][N]
__device__ float g_bkqv[N3];
__device__ float g_bfused[N3];
__device__ float g_zero[N3];

__device__ __forceinline__ void split1(float v, bf16& h, bf16& l) {
    h = __float2bfloat16_rn(v);
    l = __float2bfloat16_rn(v - __bfloat162float(h));
}

// ---------------- fp32 -> hi/lo bf16 split ----------------
__global__ void split_kernel(const float* __restrict__ src, bf16* __restrict__ dh,
                             bf16* __restrict__ dl, int n) {
    int i = (blockIdx.x * blockDim.x + threadIdx.x) * 4;
    if (i >= n) return;
    float4 v = *(const float4*)(src + i);
    bf16 h0, l0, h1, l1, h2, l2, h3, l3;
    split1(v.x, h0, l0); split1(v.y, h1, l1);
    split1(v.z, h2, l2); split1(v.w, h3, l3);
    uint32_t hh0 = (uint32_t)__bfloat16_as_ushort(h0) | ((uint32_t)__bfloat16_as_ushort(h1) << 16);
    uint32_t hh1 = (uint32_t)__bfloat16_as_ushort(h2) | ((uint32_t)__bfloat16_as_ushort(h3) << 16);
    uint32_t ll0 = (uint32_t)__bfloat16_as_ushort(l0) | ((uint32_t)__bfloat16_as_ushort(l1) << 16);
    uint32_t ll1 = (uint32_t)__bfloat16_as_ushort(l2) | ((uint32_t)__bfloat16_as_ushort(l3) << 16);
    *(uint2*)(dh + i) = make_uint2(hh0, hh1);
    *(uint2*)(dl + i) = make_uint2(ll0, ll1);
}

// ---------------- weight repack + split ----------------
__global__ void repack_split_kernel(const float* __restrict__ Wk, const float* __restrict__ Wq,
                                    const float* __restrict__ Wv, const float* __restrict__ bk,
                                    const float* __restrict__ bq, const float* __restrict__ bv) {
    int idx = blockIdx.x * blockDim.x + threadIdx.x;
    const int per = H_ * D_ * HD_;
    if (idx < 3 * per) {
        int w  = idx / per;
        int r  = idx % per;
        int h  = r / (D_ * HD_);
        int r2 = r % (D_ * HD_);
        int d  = r2 / HD_;
        int e  = r2 % HD_;
        const float* src = (w == 0) ? Wk : ((w == 1) ? Wq : Wv);
        float v = src[h * D_ * HD_ + d * HD_ + e];
        bf16 hh, ll;
        split1(v, hh, ll);
        int o = d * N3 + w * D_ + h * HD_ + e;
        g_wkh[o] = hh;
        g_wkl[o] = ll;
    }
    if (idx < N3) {
        int w = idx / D_;
        int c = idx % D_;
        const float* bsrc = (w == 0) ? bk : ((w == 1) ? bq : bv);
        g_bkqv[idx] = bsrc[c];
    }
}

// ---------------- fused bias: b' = bi @ Wkqv + bkqv ----------------
__global__ void bias_fuse_kernel(const float* __restrict__ bi) {
    int n = blockIdx.x * blockDim.x + threadIdx.x;
    if (n >= N3) return;
    float acc = g_bkqv[n];
    for (int d = 0; d < D_; d++)
        acc += bi[d] * (__bfloat162float(g_wkh[d * N3 + n]) +
                        __bfloat162float(g_wkl[d * N3 + n]));
    g_bfused[n] = acc;
}

// ---------------- MMA / cp.async helpers ----------------
__device__ __forceinline__ void mma_bf16(float* d, const uint32_t* a, const uint32_t* b) {
    asm volatile("mma.sync.aligned.m16n8k16.row.col.f32.bf16.bf16.f32 "
                 "{%0,%1,%2,%3}, {%4,%5,%6,%7}, {%8,%9}, {%0,%1,%2,%3};"
                 : "+f"(d[0]), "+f"(d[1]), "+f"(d[2]), "+f"(d[3])
                 : "r"(a[0]), "r"(a[1]), "r"(a[2]), "r"(a[3]), "r"(b[0]), "r"(b[1]));
}

__device__ __forceinline__ void cp16(uint32_t dst, const void* src) {
    asm volatile("cp.async.cg.shared.global [%0], [%1], 16;" :: "r"(dst), "l"(src));
}
__device__ __forceinline__ void cp_commit() { asm volatile("cp.async.commit_group;"); }
template <int N> __device__ __forceinline__ void cp_wait() {
    asm volatile("cp.async.wait_group %0;" :: "n"(N));
}

// =======================================================================
// GEMM: block 128x256x32, 512 threads (16 warps, warp tile 64x32 = R9 inner
// loop), 1 CTA/SM, 3-stage cp.async pipeline.
// smem/stage: A 128 rows x 128B (hi 4 | lo 4 chunks, XOR swizzle)   = 16KB
//             B 32 rows x 1024B (hi 32 | lo 32 chunks, XOR swizzle) = 32KB
// =======================================================================
#define GBM 128
#define GBN 256
#define GBK 32
#define GT  512
#define SB_OFF 16384
#define STAGE 49152
#define NSTG 3
#define GEMM_SMEM (NSTG * STAGE)

__device__ __forceinline__ void g_ldmA(uint32_t* r, uint32_t sA, int m0, int kk, int hl, int lane) {
    int mrow  = m0 + (lane & 7) + ((lane >> 3) & 1) * 8;
    int chunk = ((kk >> 3) + (lane >> 4) + hl * 4) ^ (mrow & 7);
    uint32_t addr = sA + mrow * 128 + chunk * 16;
    asm volatile("ldmatrix.sync.aligned.m8n8.x4.shared.b16 {%0,%1,%2,%3}, [%4];"
                 : "=r"(r[0]), "=r"(r[1]), "=r"(r[2]), "=r"(r[3]) : "r"(addr));
}

__device__ __forceinline__ void g_ldmB(uint32_t* b0, uint32_t* b1, uint32_t sB,
                                       int kk, int nb, int hl, int lane) {
    int krow  = kk + (lane & 7) + ((lane >> 3) & 1) * 8;
    int nc    = nb + (lane >> 4) * 8;
    int chunk = ((nc >> 3) ^ (krow & 7)) + hl * 32;
    uint32_t addr = sB + krow * 1024 + chunk * 16;
    uint32_t r0, r1, r2, r3;
    asm volatile("ldmatrix.sync.aligned.m8n8.x4.trans.shared.b16 {%0,%1,%2,%3}, [%4];"
                 : "=r"(r0), "=r"(r1), "=r"(r2), "=r"(r3) : "r"(addr));
    b0[0] = r0; b0[1] = r1; b1[0] = r2; b1[1] = r3;
}

// OM: 0 = fp32 C, 1 = hi/lo bf16 C
template <int OM>
__global__ void __launch_bounds__(GT, 1)
gemm_pre(int M, int N, int K,
         const bf16* __restrict__ Ah, const bf16* __restrict__ Al,
         const bf16* __restrict__ Bh, const bf16* __restrict__ Bl,
         const float* __restrict__ bias, float* __restrict__ C,
         bf16* __restrict__ Ch, bf16* __restrict__ Cl) {
    extern __shared__ char sm[];
    const int tid = threadIdx.x, lane = tid & 31, wid = tid >> 5;
    const int bm = blockIdx.y, bn = blockIdx.x;
    const int warp_m = wid >> 3, warp_n = wid & 7;   // 2 x 8 warps -> 64x32 tiles
    uint32_t sbase = (uint32_t)__cvta_generic_to_shared(sm);

    // fill mappings
    const int aRow = tid >> 2, aP = tid & 3;         // A: 4 threads/row
    const int aHL  = aP >> 1,  aJB = (aP & 1) * 2;   //   hi/lo + chunk-pair
    const int bKr  = tid >> 4, bPiece = tid & 15;    // B: 16 threads/row
    const int bHL  = bPiece >> 3, bQ = bPiece & 7;   //   hi/lo + 4-chunk quarter

    const bf16* Asrc = (aHL ? Al : Ah) + (size_t)(bm * GBM + aRow) * K;
    const bf16* Bsrc = (bHL ? Bl : Bh) + (size_t)bKr * N + bn * GBN;

    auto fill = [&](int buf, int kt) {
        uint32_t sA = sbase + buf * STAGE;
        uint32_t sB = sA + SB_OFF;
        const bf16* a = Asrc + kt * GBK;
        #pragma unroll
        for (int jj = 0; jj < 2; jj++) {
            int j = aJB + jj;
            int chunk = ((aHL * 4 + j) ^ (aRow & 7));
            cp16(sA + aRow * 128 + chunk * 16, a + j * 8);
        }
        const bf16* b = Bsrc + (size_t)kt * GBK * N;
        #pragma unroll
        for (int i = 0; i < 4; i++) {
            int c0 = bQ * 4 + i;                               // 0..31
            int chunk = (c0 ^ (bKr & 7)) + bHL * 32;
            cp16(sB + bKr * 1024 + chunk * 16, b + c0 * 8);
        }
        cp_commit();
    };

    float acc[4][4][4] = {};
    const int NT = K / GBK;

    fill(0, 0);
    if (NT > 1) fill(1, 1);

    for (int kt = 0; kt < NT; kt++) {
        const int cur = kt % NSTG;
        if (kt + 2 < NT)      { fill((kt + 2) % NSTG, kt + 2); cp_wait<2>(); }
        else if (kt + 1 < NT) { cp_wait<1>(); }
        else                  { cp_wait<0>(); }
        __syncthreads();

        uint32_t sA = sbase + cur * STAGE;
        uint32_t sB = sA + SB_OFF;

        #pragma unroll
        for (int kk = 0; kk < GBK; kk += 16) {
            uint32_t bh[4][2], bl[4][2];
            g_ldmB(bh[0], bh[1], sB, kk, warp_n * 32,      0, lane);
            g_ldmB(bh[2], bh[3], sB, kk, warp_n * 32 + 16, 0, lane);
            g_ldmB(bl[0], bl[1], sB, kk, warp_n * 32,      1, lane);
            g_ldmB(bl[2], bl[3], sB, kk, warp_n * 32 + 16, 1, lane);
            #pragma unroll
            for (int mt = 0; mt < 4; mt++) {
                uint32_t ah[4], al[4];
                g_ldmA(ah, sA, warp_m * 64 + mt * 16, kk, 0, lane);
                g_ldmA(al, sA, warp_m * 64 + mt * 16, kk, 1, lane);
                #pragma unroll
                for (int nt = 0; nt < 4; nt++) mma_bf16(acc[mt][nt], ah, bh[nt]);
                #pragma unroll
                for (int nt = 0; nt < 4; nt++) mma_bf16(acc[mt][nt], al, bh[nt]);
                #pragma unroll
                for (int nt = 0; nt < 4; nt++) mma_bf16(acc[mt][nt], ah, bl[nt]);
            }
        }
        __syncthreads();
    }

    #pragma unroll
    for (int mt = 0; mt < 4; mt++) {
        int r0 = bm * GBM + warp_m * 64 + mt * 16 + (lane >> 2);
        #pragma unroll
        for (int nt = 0; nt < 4; nt++) {
            int c = bn * GBN + warp_n * 32 + nt * 8 + (lane & 3) * 2;
            float2 b2 = *(const float2*)(bias + c);
            float v00 = acc[mt][nt][0] + b2.x, v01 = acc[mt][nt][1] + b2.y;
            float v10 = acc[mt][nt][2] + b2.x, v11 = acc[mt][nt][3] + b2.y;
            if (OM == 0) {
                *(float2*)(C + (size_t)r0 * N + c)       = make_float2(v00, v01);
                *(float2*)(C + (size_t)(r0 + 8) * N + c) = make_float2(v10, v11);
            } else {
                bf16 h0, l0, h1, l1;
                split1(v00, h0, l0); split1(v01, h1, l1);
                *(uint32_t*)(Ch + (size_t)r0 * N + c) =
                    (uint32_t)__bfloat16_as_ushort(h0) | ((uint32_t)__bfloat16_as_ushort(h1) << 16);
                *(uint32_t*)(Cl + (size_t)r0 * N + c) =
                    (uint32_t)__bfloat16_as_ushort(l0) | ((uint32_t)__bfloat16_as_ushort(l1) << 16);
                split1(v10, h0, l0); split1(v11, h1, l1);
                *(uint32_t*)(Ch + (size_t)(r0 + 8) * N + c) =
                    (uint32_t)__bfloat16_as_ushort(h0) | ((uint32_t)__bfloat16_as_ushort(h1) << 16);
                *(uint32_t*)(Cl + (size_t)(r0 + 8) * N + c) =
                    (uint32_t)__bfloat16_as_ushort(l0) | ((uint32_t)__bfloat16_as_ushort(l1) << 16);
            }
        }
    }
}

// =======================================================================
// Tensor-core flash attention, 128-row t-tiles (unchanged from R9)
// =======================================================================
#define ATT_K 16384
#define ATT_Q 8192
#define ATT_SMEM (2 * ATT_K + 4 * ATT_Q)

__device__ __forceinline__ void ldmKA(uint32_t* r, uint32_t base, int m0, int kk, int lane) {
    int mrow  = m0 + (lane & 7) + ((lane >> 3) & 1) * 8;
    int chunk = ((kk >> 3) + (lane >> 4)) ^ (mrow & 7);
    uint32_t addr = base + mrow * 128 + chunk * 16;
    asm volatile("ldmatrix.sync.aligned.m8n8.x4.shared.b16 {%0,%1,%2,%3}, [%4];"
                 : "=r"(r[0]), "=r"(r[1]), "=r"(r[2]), "=r"(r[3]) : "r"(addr));
}

__device__ __forceinline__ void ldmQB(uint32_t* t0, uint32_t* t1, uint32_t base,
                                      int n0, int kk, int lane) {
    int g     = lane >> 3;
    int nrow  = n0 + (lane & 7) + (g >> 1) * 8;
    int chunk = ((kk >> 3) + (g & 1)) ^ (nrow & 7);
    uint32_t addr = base + nrow * 128 + chunk * 16;
    uint32_t r0, r1, r2, r3;
    asm volatile("ldmatrix.sync.aligned.m8n8.x4.shared.b16 {%0,%1,%2,%3}, [%4];"
                 : "=r"(r0), "=r"(r1), "=r"(r2), "=r"(r3) : "r"(addr));
    t0[0] = r0; t0[1] = r1; t1[0] = r2; t1[1] = r3;
}

__device__ __forceinline__ void ldmVB(uint32_t* t0, uint32_t* t1, uint32_t base,
                                      int kk, int nb, int lane) {
    int krow  = kk + (lane & 7) + ((lane >> 3) & 1) * 8;
    int nc    = nb + (lane >> 4) * 8;
    int chunk = (nc >> 3) ^ (krow & 7);
    uint32_t addr = base + krow * 128 + chunk * 16;
    uint32_t r0, r1, r2, r3;
    asm volatile("ldmatrix.sync.aligned.m8n8.x4.trans.shared.b16 {%0,%1,%2,%3}, [%4];"
                 : "=r"(r0), "=r"(r1), "=r"(r2), "=r"(r3) : "r"(addr));
    t0[0] = r0; t0[1] = r1; t1[0] = r2; t1[1] = r3;
}

__device__ __forceinline__ void copy_half_row(const bf16* __restrict__ src,
                                              char* dst_base, int row, int half) {
    #pragma unroll
    for (int j = 0; j < 4; j++) {
        int chunk = (half * 4 + j) ^ (row & 7);
        *(uint4*)(dst_base + row * 128 + chunk * 16) = *(const uint4*)(src + j * 8);
    }
}

__global__ void __launch_bounds__(256)
attn_tc(const bf16* __restrict__ kqvh, const bf16* __restrict__ kqvl,
        bf16* __restrict__ outh, bf16* __restrict__ outl) {
    extern __shared__ __align__(16) char smem[];
    char* p_kh = smem;
    char* p_kl = smem + ATT_K;
    char* p_qh = smem + 2 * ATT_K;
    char* p_ql = p_qh + ATT_Q;
    char* p_vh = p_ql + ATT_Q;
    char* p_vl = p_vh + ATT_Q;

    const int tid = threadIdx.x, lane = tid & 31, w = tid >> 5;
    const int tchunk = blockIdx.x, h = blockIdx.y, b = blockIdx.z;
    const int tbase = tchunk * 128;

    uint32_t sb = (uint32_t)__cvta_generic_to_shared(smem);
    uint32_t s_kh = sb,             s_kl = sb + ATT_K;
    uint32_t s_qh = sb + 2 * ATT_K, s_ql = s_qh + ATT_Q;
    uint32_t s_vh = s_ql + ATT_Q,   s_vl = s_vh + ATT_Q;

    {
        int row = tid >> 1, half = tid & 1;
        size_t off = (size_t)(b * T_ + tbase + row) * N3 + h * HD_ + half * 32;
        copy_half_row(kqvh + off, p_kh, row, half);
        copy_half_row(kqvl + off, p_kl, row, half);
    }
    __syncthreads();

    uint32_t kh[4][4], kl[4][4];
    #pragma unroll
    for (int ks = 0; ks < 4; ks++) {
        ldmKA(kh[ks], s_kh, w * 16, ks * 16, lane);
        ldmKA(kl[ks], s_kl, w * 16, ks * 16, lane);
    }

    float O[8][4];
    #pragma unroll
    for (int nt = 0; nt < 8; nt++)
        #pragma unroll
        for (int j = 0; j < 4; j++) O[nt][j] = 0.f;
    float m0 = NEG_INF, m1 = NEG_INF, l0 = 0.f, l1 = 0.f;

    const int qrow = tid >> 2, qq = tid & 3;
    const int cmax = 2 * tchunk + 1;

    for (int c = 0; c <= cmax; c++) {
        __syncthreads();
        {
            size_t off = (size_t)(b * T_ + c * 64 + qrow) * N3 + D_ + h * HD_;
            #pragma unroll
            for (int jj = 0; jj < 2; jj++) {
                int j = qq * 2 + jj;
                int chunk = j ^ (qrow & 7);
                int doff = qrow * 128 + chunk * 16;
                *(uint4*)(p_qh + doff) = *(const uint4*)(kqvh + off + j * 8);
                *(uint4*)(p_ql + doff) = *(const uint4*)(kqvl + off + j * 8);
                *(uint4*)(p_vh + doff) = *(const uint4*)(kqvh + off + D_ + j * 8);
                *(uint4*)(p_vl + doff) = *(const uint4*)(kqvl + off + D_ + j * 8);
            }
        }
        __syncthreads();

        if (c * 64 > tbase + w * 16 + 15) continue;

        float sa[8][4];
        #pragma unroll
        for (int nt = 0; nt < 8; nt++)
            #pragma unroll
            for (int j = 0; j < 4; j++) sa[nt][j] = 0.f;

        #pragma unroll
        for (int ks = 0; ks < 4; ks++) {
            uint32_t bq[8][2];
            #pragma unroll
            for (int np = 0; np < 4; np++)
                ldmQB(bq[2 * np], bq[2 * np + 1], s_qh, np * 16, ks * 16, lane);
            #pragma unroll
            for (int nt = 0; nt < 8; nt++) mma_bf16(sa[nt], kh[ks], bq[nt]);
            #pragma unroll
            for (int nt = 0; nt < 8; nt++) mma_bf16(sa[nt], kl[ks], bq[nt]);
            #pragma unroll
            for (int np = 0; np < 4; np++)
                ldmQB(bq[2 * np], bq[2 * np + 1], s_ql, np * 16, ks * 16, lane);
            #pragma unroll
            for (int nt = 0; nt < 8; nt++) mma_bf16(sa[nt], kh[ks], bq[nt]);
        }

        if (c * 64 + 63 > tbase + w * 16) {
            int rg = tbase + w * 16 + (lane >> 2);
            #pragma unroll
            for (int nt = 0; nt < 8; nt++) {
                int sg = c * 64 + nt * 8 + (lane & 3) * 2;
                if (sg + 0 > rg)     sa[nt][0] = NEG_INF;
                if (sg + 1 > rg)     sa[nt][1] = NEG_INF;
                if (sg + 0 > rg + 8) sa[nt][2] = NEG_INF;
                if (sg + 1 > rg + 8) sa[nt][3] = NEG_INF;
            }
        }

        float cm0 = NEG_INF, cm1 = NEG_INF;
        #pragma unroll
        for (int nt = 0; nt < 8; nt++) {
            cm0 = fmaxf(cm0, fmaxf(sa[nt][0], sa[nt][1]));
            cm1 = fmaxf(cm1, fmaxf(sa[nt][2], sa[nt][3]));
        }
        cm0 = fmaxf(cm0, __shfl_xor_sync(0xffffffffu, cm0, 1));
        cm0 = fmaxf(cm0, __shfl_xor_sync(0xffffffffu, cm0, 2));
        cm1 = fmaxf(cm1, __shfl_xor_sync(0xffffffffu, cm1, 1));
        cm1 = fmaxf(cm1, __shfl_xor_sync(0xffffffffu, cm1, 2));

        float mn0 = fmaxf(m0, cm0), mn1 = fmaxf(m1, cm1);
        float al0 = __expf(m0 - mn0), al1 = __expf(m1 - mn1);
        m0 = mn0; m1 = mn1;
        l0 *= al0; l1 *= al1;
        #pragma unroll
        for (int nt = 0; nt < 8; nt++) {
            O[nt][0] *= al0; O[nt][1] *= al0;
            O[nt][2] *= al1; O[nt][3] *= al1;
        }

        #pragma unroll
        for (int nt = 0; nt < 8; nt++) {
            sa[nt][0] = __expf(sa[nt][0] - m0);
            sa[nt][1] = __expf(sa[nt][1] - m0);
            sa[nt][2] = __expf(sa[nt][2] - m1);
            sa[nt][3] = __expf(sa[nt][3] - m1);
            l0 += sa[nt][0] + sa[nt][1];
            l1 += sa[nt][2] + sa[nt][3];
        }

        #pragma unroll
        for (int ks = 0; ks < 4; ks++) {
            uint32_t ah[4], al[4];
            #pragma unroll
            for (int q = 0; q < 2; q++) {
                float p0 = sa[2 * ks][2 * q],     p1 = sa[2 * ks][2 * q + 1];
                float p2 = sa[2 * ks + 1][2 * q], p3 = sa[2 * ks + 1][2 * q + 1];
                bf16 h0, e0, h1, e1, h2, e2, h3, e3;
                split1(p0, h0, e0); split1(p1, h1, e1);
                split1(p2, h2, e2); split1(p3, h3, e3);
                ah[q]     = (uint32_t)__bfloat16_as_ushort(h0) | ((uint32_t)__bfloat16_as_ushort(h1) << 16);
                ah[q + 2] = (uint32_t)__bfloat16_as_ushort(h2) | ((uint32_t)__bfloat16_as_ushort(h3) << 16);
                al[q]     = (uint32_t)__bfloat16_as_ushort(e0) | ((uint32_t)__bfloat16_as_ushort(e1) << 16);
                al[q + 2] = (uint32_t)__bfloat16_as_ushort(e2) | ((uint32_t)__bfloat16_as_ushort(e3) << 16);
            }
            uint32_t bv[8][2];
            #pragma unroll
            for (int np = 0; np < 4; np++)
                ldmVB(bv[2 * np], bv[2 * np + 1], s_vh, ks * 16, np * 16, lane);
            #pragma unroll
            for (int nt = 0; nt < 8; nt++) mma_bf16(O[nt], ah, bv[nt]);
            #pragma unroll
            for (int nt = 0; nt < 8; nt++) mma_bf16(O[nt], al, bv[nt]);
            #pragma unroll
            for (int np = 0; np < 4; np++)
                ldmVB(bv[2 * np], bv[2 * np + 1], s_vl, ks * 16, np * 16, lane);
            #pragma unroll
            for (int nt = 0; nt < 8; nt++) mma_bf16(O[nt], ah, bv[nt]);
        }
    }

    l0 += __shfl_xor_sync(0xffffffffu, l0, 1);
    l0 += __shfl_xor_sync(0xffffffffu, l0, 2);
    l1 += __shfl_xor_sync(0xffffffffu, l1, 1);
    l1 += __shfl_xor_sync(0xffffffffu, l1, 2);
    float inv0 = 1.f / l0, inv1 = 1.f / l1;

    int r0 = tbase + w * 16 + (lane >> 2);
    #pragma unroll
    for (int nt = 0; nt < 8; nt++) {
        int col = h * HD_ + nt * 8 + (lane & 3) * 2;
        float v00 = O[nt][0] * inv0, v01 = O[nt][1] * inv0;
        float v10 = O[nt][2] * inv1, v11 = O[nt][3] * inv1;
        bf16 h0, e0, h1, e1;
        split1(v00, h0, e0); split1(v01, h1, e1);
        *(uint32_t*)(outh + (size_t)(b * T_ + r0) * D_ + col) =
            (uint32_t)__bfloat16_as_ushort(h0) | ((uint32_t)__bfloat16_as_ushort(h1) << 16);
        *(uint32_t*)(outl + (size_t)(b * T_ + r0) * D_ + col) =
            (uint32_t)__bfloat16_as_ushort(e0) | ((uint32_t)__bfloat16_as_ushort(e1) << 16);
        split1(v10, h0, e0); split1(v11, h1, e1);
        *(uint32_t*)(outh + (size_t)(b * T_ + r0 + 8) * D_ + col) =
            (uint32_t)__bfloat16_as_ushort(h0) | ((uint32_t)__bfloat16_as_ushort(h1) << 16);
        *(uint32_t*)(outl + (size_t)(b * T_ + r0 + 8) * D_ + col) =
            (uint32_t)__bfloat16_as_ushort(e0) | ((uint32_t)__bfloat16_as_ushort(e1) << 16);
    }
}

// ---------------- launch ----------------
extern "C" void kernel_launch(void* const* d_in, const int* in_sizes, int n_in,
                              void* d_out, int out_size) {
    const float* x  = (const float*)d_in[0];
    const float* Wi = (const float*)d_in[1];
    const float* bi = (const float*)d_in[2];
    const float* Wk = (const float*)d_in[3];
    const float* bk = (const float*)d_in[4];
    const float* Wq = (const float*)d_in[5];
    const float* bq = (const float*)d_in[6];
    const float* Wv = (const float*)d_in[7];
    const float* bv = (const float*)d_in[8];
    const float* Wo = (const float*)d_in[9];
    const float* bo = (const float*)d_in[10];
    float* out = (float*)d_out;

    bf16 *p_xh, *p_xl, *p_kqvh, *p_kqvl, *p_ah, *p_al;
    bf16 *p_wih, *p_wil, *p_wkh, *p_wkl, *p_wph, *p_wpl, *p_woh, *p_wol;
    float *p_bfused, *p_zero;
    cudaGetSymbolAddress((void**)&p_xh, g_xh);     cudaGetSymbolAddress((void**)&p_xl, g_xl);
    cudaGetSymbolAddress((void**)&p_kqvh, g_kqvh); cudaGetSymbolAddress((void**)&p_kqvl, g_kqvl);
    cudaGetSymbolAddress((void**)&p_ah, g_ah);     cudaGetSymbolAddress((void**)&p_al, g_al);
    cudaGetSymbolAddress((void**)&p_wih, g_wih);   cudaGetSymbolAddress((void**)&p_wil, g_wil);
    cudaGetSymbolAddress((void**)&p_wkh, g_wkh);   cudaGetSymbolAddress((void**)&p_wkl, g_wkl);
    cudaGetSymbolAddress((void**)&p_wph, g_wph);   cudaGetSymbolAddress((void**)&p_wpl, g_wpl);
    cudaGetSymbolAddress((void**)&p_woh, g_woh);   cudaGetSymbolAddress((void**)&p_wol, g_wol);
    cudaGetSymbolAddress((void**)&p_bfused, g_bfused);
    cudaGetSymbolAddress((void**)&p_zero, g_zero);

    static bool attr_set = false;
    if (!attr_set) {
        cudaFuncSetAttribute(gemm_pre<0>, cudaFuncAttributeMaxDynamicSharedMemorySize, GEMM_SMEM);
        cudaFuncSetAttribute(gemm_pre<1>, cudaFuncAttributeMaxDynamicSharedMemorySize, GEMM_SMEM);
        cudaFuncSetAttribute(attn_tc,     cudaFuncAttributeMaxDynamicSharedMemorySize, ATT_SMEM);
        attr_set = true;
    }

    // splits / repack
    split_kernel<<<(M_ * D_ / 4 + 255) / 256, 256>>>(x,  p_xh,  p_xl,  M_ * D_);
    split_kernel<<<(D_ * D_ / 4 + 255) / 256, 256>>>(Wi, p_wih, p_wil, D_ * D_);
    split_kernel<<<(D_ * D_ / 4 + 255) / 256, 256>>>(Wo, p_woh, p_wol, D_ * D_);
    repack_split_kernel<<<(3 * H_ * D_ * HD_ + 255) / 256, 256>>>(Wk, Wq, Wv, bk, bq, bv);
    bias_fuse_kernel<<<(N3 + 255) / 256, 256>>>(bi);

    {   // W' = Wi @ Wkqv  -> hi/lo   [1024 x 3072]
        dim3 grid(N3 / GBN, D_ / GBM);
        gemm_pre<1><<<grid, GT, GEMM_SMEM>>>(D_, N3, D_, p_wih, p_wil, p_wkh, p_wkl,
                                             p_zero, nullptr, p_wph, p_wpl);
    }
    {   // kqv = x @ W' + b'  -> hi/lo   [16384 x 3072]
        dim3 grid(N3 / GBN, M_ / GBM);
        gemm_pre<1><<<grid, GT, GEMM_SMEM>>>(M_, N3, D_, p_xh, p_xl, p_wph, p_wpl,
                                             p_bfused, nullptr, p_kqvh, p_kqvl);
    }
    {   // attention -> hi/lo  (128-row t-tiles)
        dim3 grid(T_ / 128, H_, B_);
        attn_tc<<<grid, 256, ATT_SMEM>>>(p_kqvh, p_kqvl, p_ah, p_al);
    }
    {   // out = attn @ Wo + bo -> fp32
        dim3 grid(D_ / GBN, M_ / GBM);
        gemm_pre<0><<<grid, GT, GEMM_SMEM>>>(M_, D_, D_, p_ah, p_al, p_woh, p_wol,
                                             bo, out, nullptr, nullptr);
    }
}

// round 15
// speedup vs baseline: 2.2668x; 1.2431x over previous
#include <cuda_runtime.h>
#include <cuda_fp16.h>
#include <math.h>
#include <stdint.h>

#define B_  32
#define T_  512
#define D_  1024
#define H_  16
#define HD_ 64
#define M_  (B_ * T_)      // 16384
#define N3  (3 * D_)       // 3072

#define NEG_INF __int_as_float(0xff800000)

typedef __half fp16;

// ---------------- device scratch ----------------
__device__ fp16 g_xh[M_ * D_],   g_xl[M_ * D_];
__device__ fp16 g_kqvh[M_ * N3], g_kqvl[M_ * N3];
__device__ fp16 g_ah[M_ * D_],   g_al[M_ * D_];
__device__ fp16 g_wih[D_ * D_],  g_wil[D_ * D_];    // Wi [K][N] row-major
__device__ fp16 g_wkh[D_ * N3],  g_wkl[D_ * N3];    // repacked Wkqv [K][N]
__device__ fp16 g_wph[D_ * N3],  g_wpl[D_ * N3];    // fused W' = Wi@Wkqv
__device__ fp16 g_woh[D_ * D_],  g_wol[D_ * D_];    // Wo [K][N]
__device__ float g_bkqv[N3];
__device__ float g_bfused[N3];
__device__ float g_zero[N3];

__device__ __forceinline__ void split1(float v, fp16& h, fp16& l) {
    h = __float2half_rn(v);
    l = __float2half_rn(v - __half2float(h));
}
__device__ __forceinline__ uint32_t pack2(fp16 a, fp16 b) {
    return (uint32_t)__half_as_ushort(a) | ((uint32_t)__half_as_ushort(b) << 16);
}

// ---------------- fp32 -> hi/lo fp16 split ----------------
__global__ void split_kernel(const float* __restrict__ src, fp16* __restrict__ dh,
                             fp16* __restrict__ dl, int n) {
    int i = (blockIdx.x * blockDim.x + threadIdx.x) * 4;
    if (i >= n) return;
    float4 v = *(const float4*)(src + i);
    fp16 h0, l0, h1, l1, h2, l2, h3, l3;
    split1(v.x, h0, l0); split1(v.y, h1, l1);
    split1(v.z, h2, l2); split1(v.w, h3, l3);
    *(uint2*)(dh + i) = make_uint2(pack2(h0, h1), pack2(h2, h3));
    *(uint2*)(dl + i) = make_uint2(pack2(l0, l1), pack2(l2, l3));
}

// ---------------- weight repack + split ----------------
__global__ void repack_split_kernel(const float* __restrict__ Wk, const float* __restrict__ Wq,
                                    const float* __restrict__ Wv, const float* __restrict__ bk,
                                    const float* __restrict__ bq, const float* __restrict__ bv) {
    int idx = blockIdx.x * blockDim.x + threadIdx.x;
    const int per = H_ * D_ * HD_;
    if (idx < 3 * per) {
        int w  = idx / per;
        int r  = idx % per;
        int h  = r / (D_ * HD_);
        int r2 = r % (D_ * HD_);
        int d  = r2 / HD_;
        int e  = r2 % HD_;
        const float* src = (w == 0) ? Wk : ((w == 1) ? Wq : Wv);
        float v = src[h * D_ * HD_ + d * HD_ + e];
        fp16 hh, ll;
        split1(v, hh, ll);
        int o = d * N3 + w * D_ + h * HD_ + e;
        g_wkh[o] = hh;
        g_wkl[o] = ll;
    }
    if (idx < N3) {
        int w = idx / D_;
        int c = idx % D_;
        const float* bsrc = (w == 0) ? bk : ((w == 1) ? bq : bv);
        g_bkqv[idx] = bsrc[c];
    }
}

// ---------------- fused bias: b' = bi @ Wkqv + bkqv ----------------
__global__ void bias_fuse_kernel(const float* __restrict__ bi) {
    int n = blockIdx.x * blockDim.x + threadIdx.x;
    if (n >= N3) return;
    float acc = g_bkqv[n];
    for (int d = 0; d < D_; d++)
        acc += bi[d] * (__half2float(g_wkh[d * N3 + n]) +
                        __half2float(g_wkl[d * N3 + n]));
    g_bfused[n] = acc;
}

// ---------------- MMA / cp.async helpers ----------------
__device__ __forceinline__ void mma_f16(float* d, const uint32_t* a, const uint32_t* b) {
    asm volatile("mma.sync.aligned.m16n8k16.row.col.f32.f16.f16.f32 "
                 "{%0,%1,%2,%3}, {%4,%5,%6,%7}, {%8,%9}, {%0,%1,%2,%3};"
                 : "+f"(d[0]), "+f"(d[1]), "+f"(d[2]), "+f"(d[3])
                 : "r"(a[0]), "r"(a[1]), "r"(a[2]), "r"(a[3]), "r"(b[0]), "r"(b[1]));
}

__device__ __forceinline__ void cp16(uint32_t dst, const void* src) {
    asm volatile("cp.async.cg.shared.global [%0], [%1], 16;" :: "r"(dst), "l"(src));
}
__device__ __forceinline__ void cp_commit() { asm volatile("cp.async.commit_group;"); }
template <int N> __device__ __forceinline__ void cp_wait() {
    asm volatile("cp.async.wait_group %0;" :: "n"(N));
}

// common ldmatrix helpers (A from 128B-row layout; B-hi from 512B rows;
// B pair (hi|lo) from 1024B rows)
__device__ __forceinline__ void g_ldmA(uint32_t* r, uint32_t sA, int m0, int kk, int hl, int lane) {
    int mrow  = m0 + (lane & 7) + ((lane >> 3) & 1) * 8;
    int chunk = ((kk >> 3) + (lane >> 4) + hl * 4) ^ (mrow & 7);
    uint32_t addr = sA + mrow * 128 + chunk * 16;
    asm volatile("ldmatrix.sync.aligned.m8n8.x4.shared.b16 {%0,%1,%2,%3}, [%4];"
                 : "=r"(r[0]), "=r"(r[1]), "=r"(r[2]), "=r"(r[3]) : "r"(addr));
}

__device__ __forceinline__ void g_ldmB512(uint32_t* b0, uint32_t* b1, uint32_t sB,
                                          int kk, int nb, int lane) {
    int krow  = kk + (lane & 7) + ((lane >> 3) & 1) * 8;
    int nc    = nb + (lane >> 4) * 8;
    int chunk = (nc >> 3) ^ (krow & 7);
    uint32_t addr = sB + krow * 512 + chunk * 16;
    uint32_t r0, r1, r2, r3;
    asm volatile("ldmatrix.sync.aligned.m8n8.x4.trans.shared.b16 {%0,%1,%2,%3}, [%4];"
                 : "=r"(r0), "=r"(r1), "=r"(r2), "=r"(r3) : "r"(addr));
    b0[0] = r0; b0[1] = r1; b1[0] = r2; b1[1] = r3;
}

__device__ __forceinline__ void g_ldmB1024(uint32_t* b0, uint32_t* b1, uint32_t sB,
                                           int kk, int nb, int hl, int lane) {
    int krow  = kk + (lane & 7) + ((lane >> 3) & 1) * 8;
    int nc    = nb + (lane >> 4) * 8;
    int chunk = ((nc >> 3) ^ (krow & 7)) + hl * 32;
    uint32_t addr = sB + krow * 1024 + chunk * 16;
    uint32_t r0, r1, r2, r3;
    asm volatile("ldmatrix.sync.aligned.m8n8.x4.trans.shared.b16 {%0,%1,%2,%3}, [%4];"
                 : "=r"(r0), "=r"(r1), "=r"(r2), "=r"(r3) : "r"(addr));
    b0[0] = r0; b0[1] = r1; b1[0] = r2; b1[1] = r3;
}

// =======================================================================
// GEMM variant A: fp16 2-combo  C = (Ah+Al)@Bh + bias
// Block 128x256x32, 512 thr, 4-stage. Stage: A 16KB | B-hi 16KB = 32KB.
// =======================================================================
#define GBM 128
#define GBN 256
#define GBK 32
#define GT  512
#define G2_STAGE 32768
#define G2_NSTG 4
#define G2_SMEM (G2_NSTG * G2_STAGE)

template <int OM>   // 0: fp32 C, 1: hi/lo fp16 C
__global__ void __launch_bounds__(GT, 1)
gemm2_pre(int M, int N, int K,
          const fp16* __restrict__ Ah, const fp16* __restrict__ Al,
          const fp16* __restrict__ Bh,
          const float* __restrict__ bias, float* __restrict__ C,
          fp16* __restrict__ Ch, fp16* __restrict__ Cl) {
    extern __shared__ char sm[];
    const int tid = threadIdx.x, lane = tid & 31, wid = tid >> 5;
    const int bm = blockIdx.y, bn = blockIdx.x;
    const int warp_m = wid >> 3, warp_n = wid & 7;
    uint32_t sbase = (uint32_t)__cvta_generic_to_shared(sm);

    const int aRow = tid >> 2, aP = tid & 3;
    const int aHL  = aP >> 1,  aJB = (aP & 1) * 2;
    const int bKr  = tid >> 4, bPiece = tid & 15;

    const fp16* Asrc = (aHL ? Al : Ah) + (size_t)(bm * GBM + aRow) * K;
    const fp16* Bsrc = Bh + (size_t)bKr * N + bn * GBN;

    auto fill = [&](int buf, int kt) {
        uint32_t sA = sbase + buf * G2_STAGE;
        uint32_t sB = sA + 16384;
        const fp16* a = Asrc + kt * GBK;
        #pragma unroll
        for (int jj = 0; jj < 2; jj++) {
            int j = aJB + jj;
            int chunk = ((aHL * 4 + j) ^ (aRow & 7));
            cp16(sA + aRow * 128 + chunk * 16, a + j * 8);
        }
        const fp16* b = Bsrc + (size_t)kt * GBK * N;
        #pragma unroll
        for (int i = 0; i < 2; i++) {
            int c0 = bPiece * 2 + i;
            int chunk = c0 ^ (bKr & 7);
            cp16(sB + bKr * 512 + chunk * 16, b + c0 * 8);
        }
        cp_commit();
    };

    float acc[4][4][4] = {};
    const int NT = K / GBK;

    fill(0, 0);
    if (NT > 1) fill(1, 1);
    if (NT > 2) fill(2, 2);

    for (int kt = 0; kt < NT; kt++) {
        const int cur = kt % G2_NSTG;
        if (kt + 3 < NT)      { fill((kt + 3) % G2_NSTG, kt + 3); cp_wait<3>(); }
        else if (kt + 2 < NT) { cp_wait<2>(); }
        else if (kt + 1 < NT) { cp_wait<1>(); }
        else                  { cp_wait<0>(); }
        __syncthreads();

        uint32_t sA = sbase + cur * G2_STAGE;
        uint32_t sB = sA + 16384;

        #pragma unroll
        for (int kk = 0; kk < GBK; kk += 16) {
            uint32_t bh[4][2];
            g_ldmB512(bh[0], bh[1], sB, kk, warp_n * 32,      lane);
            g_ldmB512(bh[2], bh[3], sB, kk, warp_n * 32 + 16, lane);
            #pragma unroll
            for (int mt = 0; mt < 4; mt++) {
                uint32_t ah[4], al[4];
                g_ldmA(ah, sA, warp_m * 64 + mt * 16, kk, 0, lane);
                g_ldmA(al, sA, warp_m * 64 + mt * 16, kk, 1, lane);
                #pragma unroll
                for (int nt = 0; nt < 4; nt++) mma_f16(acc[mt][nt], ah, bh[nt]);
                #pragma unroll
                for (int nt = 0; nt < 4; nt++) mma_f16(acc[mt][nt], al, bh[nt]);
            }
        }
        __syncthreads();
    }

    #pragma unroll
    for (int mt = 0; mt < 4; mt++) {
        int r0 = bm * GBM + warp_m * 64 + mt * 16 + (lane >> 2);
        #pragma unroll
        for (int nt = 0; nt < 4; nt++) {
            int c = bn * GBN + warp_n * 32 + nt * 8 + (lane & 3) * 2;
            float2 b2 = *(const float2*)(bias + c);
            float v00 = acc[mt][nt][0] + b2.x, v01 = acc[mt][nt][1] + b2.y;
            float v10 = acc[mt][nt][2] + b2.x, v11 = acc[mt][nt][3] + b2.y;
            if (OM == 0) {
                *(float2*)(C + (size_t)r0 * N + c)       = make_float2(v00, v01);
                *(float2*)(C + (size_t)(r0 + 8) * N + c) = make_float2(v10, v11);
            } else {
                fp16 h0, l0, h1, l1;
                split1(v00, h0, l0); split1(v01, h1, l1);
                *(uint32_t*)(Ch + (size_t)r0 * N + c) = pack2(h0, h1);
                *(uint32_t*)(Cl + (size_t)r0 * N + c) = pack2(l0, l1);
                split1(v10, h0, l0); split1(v11, h1, l1);
                *(uint32_t*)(Ch + (size_t)(r0 + 8) * N + c) = pack2(h0, h1);
                *(uint32_t*)(Cl + (size_t)(r0 + 8) * N + c) = pack2(l0, l1);
            }
        }
    }
}

// =======================================================================
// GEMM variant B: fp16 3-combo  C = AhBh + AlBh + AhBl + bias
// Block 128x256x32, 512 thr, 3-stage. Stage: A 16KB | B hi+lo 32KB = 48KB.
// =======================================================================
#define G3_STAGE 49152
#define G3_NSTG 3
#define G3_SMEM (G3_NSTG * G3_STAGE)

template <int OM>
__global__ void __launch_bounds__(GT, 1)
gemm3_pre(int M, int N, int K,
          const fp16* __restrict__ Ah, const fp16* __restrict__ Al,
          const fp16* __restrict__ Bh, const fp16* __restrict__ Bl,
          const float* __restrict__ bias, float* __restrict__ C,
          fp16* __restrict__ Ch, fp16* __restrict__ Cl) {
    extern __shared__ char sm[];
    const int tid = threadIdx.x, lane = tid & 31, wid = tid >> 5;
    const int bm = blockIdx.y, bn = blockIdx.x;
    const int warp_m = wid >> 3, warp_n = wid & 7;
    uint32_t sbase = (uint32_t)__cvta_generic_to_shared(sm);

    const int aRow = tid >> 2, aP = tid & 3;
    const int aHL  = aP >> 1,  aJB = (aP & 1) * 2;
    const int bKr  = tid >> 4, bPiece = tid & 15;
    const int bHL  = bPiece >> 3, bQ = bPiece & 7;

    const fp16* Asrc = (aHL ? Al : Ah) + (size_t)(bm * GBM + aRow) * K;
    const fp16* Bsrc = (bHL ? Bl : Bh) + (size_t)bKr * N + bn * GBN;

    auto fill = [&](int buf, int kt) {
        uint32_t sA = sbase + buf * G3_STAGE;
        uint32_t sB = sA + 16384;
        const fp16* a = Asrc + kt * GBK;
        #pragma unroll
        for (int jj = 0; jj < 2; jj++) {
            int j = aJB + jj;
            int chunk = ((aHL * 4 + j) ^ (aRow & 7));
            cp16(sA + aRow * 128 + chunk * 16, a + j * 8);
        }
        const fp16* b = Bsrc + (size_t)kt * GBK * N;
        #pragma unroll
        for (int i = 0; i < 4; i++) {
            int c0 = bQ * 4 + i;
            int chunk = (c0 ^ (bKr & 7)) + bHL * 32;
            cp16(sB + bKr * 1024 + chunk * 16, b + c0 * 8);
        }
        cp_commit();
    };

    float acc[4][4][4] = {};
    const int NT = K / GBK;

    fill(0, 0);
    if (NT > 1) fill(1, 1);

    for (int kt = 0; kt < NT; kt++) {
        const int cur = kt % G3_NSTG;
        if (kt + 2 < NT)      { fill((kt + 2) % G3_NSTG, kt + 2); cp_wait<2>(); }
        else if (kt + 1 < NT) { cp_wait<1>(); }
        else                  { cp_wait<0>(); }
        __syncthreads();

        uint32_t sA = sbase + cur * G3_STAGE;
        uint32_t sB = sA + 16384;

        #pragma unroll
        for (int kk = 0; kk < GBK; kk += 16) {
            uint32_t bh[4][2], bl[4][2];
            g_ldmB1024(bh[0], bh[1], sB, kk, warp_n * 32,      0, lane);
            g_ldmB1024(bh[2], bh[3], sB, kk, warp_n * 32 + 16, 0, lane);
            g_ldmB1024(bl[0], bl[1], sB, kk, warp_n * 32,      1, lane);
            g_ldmB1024(bl[2], bl[3], sB, kk, warp_n * 32 + 16, 1, lane);
            #pragma unroll
            for (int mt = 0; mt < 4; mt++) {
                uint32_t ah[4], al[4];
                g_ldmA(ah, sA, warp_m * 64 + mt * 16, kk, 0, lane);
                g_ldmA(al, sA, warp_m * 64 + mt * 16, kk, 1, lane);
                #pragma unroll
                for (int nt = 0; nt < 4; nt++) mma_f16(acc[mt][nt], ah, bh[nt]);
                #pragma unroll
                for (int nt = 0; nt < 4; nt++) mma_f16(acc[mt][nt], al, bh[nt]);
                #pragma unroll
                for (int nt = 0; nt < 4; nt++) mma_f16(acc[mt][nt], ah, bl[nt]);
            }
        }
        __syncthreads();
    }

    #pragma unroll
    for (int mt = 0; mt < 4; mt++) {
        int r0 = bm * GBM + warp_m * 64 + mt * 16 + (lane >> 2);
        #pragma unroll
        for (int nt = 0; nt < 4; nt++) {
            int c = bn * GBN + warp_n * 32 + nt * 8 + (lane & 3) * 2;
            float2 b2 = *(const float2*)(bias + c);
            float v00 = acc[mt][nt][0] + b2.x, v01 = acc[mt][nt][1] + b2.y;
            float v10 = acc[mt][nt][2] + b2.x, v11 = acc[mt][nt][3] + b2.y;
            if (OM == 0) {
                *(float2*)(C + (size_t)r0 * N + c)       = make_float2(v00, v01);
                *(float2*)(C + (size_t)(r0 + 8) * N + c) = make_float2(v10, v11);
            } else {
                fp16 h0, l0, h1, l1;
                split1(v00, h0, l0); split1(v01, h1, l1);
                *(uint32_t*)(Ch + (size_t)r0 * N + c) = pack2(h0, h1);
                *(uint32_t*)(Cl + (size_t)r0 * N + c) = pack2(l0, l1);
                split1(v10, h0, l0); split1(v11, h1, l1);
                *(uint32_t*)(Ch + (size_t)(r0 + 8) * N + c) = pack2(h0, h1);
                *(uint32_t*)(Cl + (size_t)(r0 + 8) * N + c) = pack2(l0, l1);
            }
        }
    }
}

// =======================================================================
// Tensor-core flash attention, 128-row t-tiles, fp16 3-combo
// =======================================================================
#define ATT_K 16384
#define ATT_Q 8192
#define ATT_SMEM (2 * ATT_K + 4 * ATT_Q)

__device__ __forceinline__ void ldmKA(uint32_t* r, uint32_t base, int m0, int kk, int lane) {
    int mrow  = m0 + (lane & 7) + ((lane >> 3) & 1) * 8;
    int chunk = ((kk >> 3) + (lane >> 4)) ^ (mrow & 7);
    uint32_t addr = base + mrow * 128 + chunk * 16;
    asm volatile("ldmatrix.sync.aligned.m8n8.x4.shared.b16 {%0,%1,%2,%3}, [%4];"
                 : "=r"(r[0]), "=r"(r[1]), "=r"(r[2]), "=r"(r[3]) : "r"(addr));
}

__device__ __forceinline__ void ldmQB(uint32_t* t0, uint32_t* t1, uint32_t base,
                                      int n0, int kk, int lane) {
    int g     = lane >> 3;
    int nrow  = n0 + (lane & 7) + (g >> 1) * 8;
    int chunk = ((kk >> 3) + (g & 1)) ^ (nrow & 7);
    uint32_t addr = base + nrow * 128 + chunk * 16;
    uint32_t r0, r1, r2, r3;
    asm volatile("ldmatrix.sync.aligned.m8n8.x4.shared.b16 {%0,%1,%2,%3}, [%4];"
                 : "=r"(r0), "=r"(r1), "=r"(r2), "=r"(r3) : "r"(addr));
    t0[0] = r0; t0[1] = r1; t1[0] = r2; t1[1] = r3;
}

__device__ __forceinline__ void ldmVB(uint32_t* t0, uint32_t* t1, uint32_t base,
                                      int kk, int nb, int lane) {
    int krow  = kk + (lane & 7) + ((lane >> 3) & 1) * 8;
    int nc    = nb + (lane >> 4) * 8;
    int chunk = (nc >> 3) ^ (krow & 7);
    uint32_t addr = base + krow * 128 + chunk * 16;
    uint32_t r0, r1, r2, r3;
    asm volatile("ldmatrix.sync.aligned.m8n8.x4.trans.shared.b16 {%0,%1,%2,%3}, [%4];"
                 : "=r"(r0), "=r"(r1), "=r"(r2), "=r"(r3) : "r"(addr));
    t0[0] = r0; t0[1] = r1; t1[0] = r2; t1[1] = r3;
}

__device__ __forceinline__ void copy_half_row(const fp16* __restrict__ src,
                                              char* dst_base, int row, int half) {
    #pragma unroll
    for (int j = 0; j < 4; j++) {
        int chunk = (half * 4 + j) ^ (row & 7);
        *(uint4*)(dst_base + row * 128 + chunk * 16) = *(const uint4*)(src + j * 8);
    }
}

__global__ void __launch_bounds__(256)
attn_tc(const fp16* __restrict__ kqvh, const fp16* __restrict__ kqvl,
        fp16* __restrict__ outh, fp16* __restrict__ outl) {
    extern __shared__ __align__(16) char smem[];
    char* p_kh = smem;
    char* p_kl = smem + ATT_K;
    char* p_qh = smem + 2 * ATT_K;
    char* p_ql = p_qh + ATT_Q;
    char* p_vh = p_ql + ATT_Q;
    char* p_vl = p_vh + ATT_Q;

    const int tid = threadIdx.x, lane = tid & 31, w = tid >> 5;
    const int tchunk = blockIdx.x, h = blockIdx.y, b = blockIdx.z;
    const int tbase = tchunk * 128;

    uint32_t sb = (uint32_t)__cvta_generic_to_shared(smem);
    uint32_t s_kh = sb,             s_kl = sb + ATT_K;
    uint32_t s_qh = sb + 2 * ATT_K, s_ql = s_qh + ATT_Q;
    uint32_t s_vh = s_ql + ATT_Q,   s_vl = s_vh + ATT_Q;

    {
        int row = tid >> 1, half = tid & 1;
        size_t off = (size_t)(b * T_ + tbase + row) * N3 + h * HD_ + half * 32;
        copy_half_row(kqvh + off, p_kh, row, half);
        copy_half_row(kqvl + off, p_kl, row, half);
    }
    __syncthreads();

    uint32_t kh[4][4], kl[4][4];
    #pragma unroll
    for (int ks = 0; ks < 4; ks++) {
        ldmKA(kh[ks], s_kh, w * 16, ks * 16, lane);
        ldmKA(kl[ks], s_kl, w * 16, ks * 16, lane);
    }

    float O[8][4];
    #pragma unroll
    for (int nt = 0; nt < 8; nt++)
        #pragma unroll
        for (int j = 0; j < 4; j++) O[nt][j] = 0.f;
    float m0 = NEG_INF, m1 = NEG_INF, l0 = 0.f, l1 = 0.f;

    const int qrow = tid >> 2, qq = tid & 3;
    const int cmax = 2 * tchunk + 1;

    for (int c = 0; c <= cmax; c++) {
        __syncthreads();
        {
            size_t off = (size_t)(b * T_ + c * 64 + qrow) * N3 + D_ + h * HD_;
            #pragma unroll
            for (int jj = 0; jj < 2; jj++) {
                int j = qq * 2 + jj;
                int chunk = j ^ (qrow & 7);
                int doff = qrow * 128 + chunk * 16;
                *(uint4*)(p_qh + doff) = *(const uint4*)(kqvh + off + j * 8);
                *(uint4*)(p_ql + doff) = *(const uint4*)(kqvl + off + j * 8);
                *(uint4*)(p_vh + doff) = *(const uint4*)(kqvh + off + D_ + j * 8);
                *(uint4*)(p_vl + doff) = *(const uint4*)(kqvl + off + D_ + j * 8);
            }
        }
        __syncthreads();

        if (c * 64 > tbase + w * 16 + 15) continue;

        float sa[8][4];
        #pragma unroll
        for (int nt = 0; nt < 8; nt++)
            #pragma unroll
            for (int j = 0; j < 4; j++) sa[nt][j] = 0.f;

        #pragma unroll
        for (int ks = 0; ks < 4; ks++) {
            uint32_t bq[8][2];
            #pragma unroll
            for (int np = 0; np < 4; np++)
                ldmQB(bq[2 * np], bq[2 * np + 1], s_qh, np * 16, ks * 16, lane);
            #pragma unroll
            for (int nt = 0; nt < 8; nt++) mma_f16(sa[nt], kh[ks], bq[nt]);
            #pragma unroll
            for (int nt = 0; nt < 8; nt++) mma_f16(sa[nt], kl[ks], bq[nt]);
            #pragma unroll
            for (int np = 0; np < 4; np++)
                ldmQB(bq[2 * np], bq[2 * np + 1], s_ql, np * 16, ks * 16, lane);
            #pragma unroll
            for (int nt = 0; nt < 8; nt++) mma_f16(sa[nt], kh[ks], bq[nt]);
        }

        if (c * 64 + 63 > tbase + w * 16) {
            int rg = tbase + w * 16 + (lane >> 2);
            #pragma unroll
            for (int nt = 0; nt < 8; nt++) {
                int sg = c * 64 + nt * 8 + (lane & 3) * 2;
                if (sg + 0 > rg)     sa[nt][0] = NEG_INF;
                if (sg + 1 > rg)     sa[nt][1] = NEG_INF;
                if (sg + 0 > rg + 8) sa[nt][2] = NEG_INF;
                if (sg + 1 > rg + 8) sa[nt][3] = NEG_INF;
            }
        }

        float cm0 = NEG_INF, cm1 = NEG_INF;
        #pragma unroll
        for (int nt = 0; nt < 8; nt++) {
            cm0 = fmaxf(cm0, fmaxf(sa[nt][0], sa[nt][1]));
            cm1 = fmaxf(cm1, fmaxf(sa[nt][2], sa[nt][3]));
        }
        cm0 = fmaxf(cm0, __shfl_xor_sync(0xffffffffu, cm0, 1));
        cm0 = fmaxf(cm0, __shfl_xor_sync(0xffffffffu, cm0, 2));
        cm1 = fmaxf(cm1, __shfl_xor_sync(0xffffffffu, cm1, 1));
        cm1 = fmaxf(cm1, __shfl_xor_sync(0xffffffffu, cm1, 2));

        float mn0 = fmaxf(m0, cm0), mn1 = fmaxf(m1, cm1);
        float al0 = __expf(m0 - mn0), al1 = __expf(m1 - mn1);
        m0 = mn0; m1 = mn1;
        l0 *= al0; l1 *= al1;
        #pragma unroll
        for (int nt = 0; nt < 8; nt++) {
            O[nt][0] *= al0; O[nt][1] *= al0;
            O[nt][2] *= al1; O[nt][3] *= al1;
        }

        #pragma unroll
        for (int nt = 0; nt < 8; nt++) {
            sa[nt][0] = __expf(sa[nt][0] - m0);
            sa[nt][1] = __expf(sa[nt][1] - m0);
            sa[nt][2] = __expf(sa[nt][2] - m1);
            sa[nt][3] = __expf(sa[nt][3] - m1);
            l0 += sa[nt][0] + sa[nt][1];
            l1 += sa[nt][2] + sa[nt][3];
        }

        #pragma unroll
        for (int ks = 0; ks < 4; ks++) {
            uint32_t ah[4], al[4];
            #pragma unroll
            for (int q = 0; q < 2; q++) {
                float p0 = sa[2 * ks][2 * q],     p1 = sa[2 * ks][2 * q + 1];
                float p2 = sa[2 * ks + 1][2 * q], p3 = sa[2 * ks + 1][2 * q + 1];
                fp16 h0, e0, h1, e1, h2, e2, h3, e3;
                split1(p0, h0, e0); split1(p1, h1, e1);
                split1(p2, h2, e2); split1(p3, h3, e3);
                ah[q]     = pack2(h0, h1);
                ah[q + 2] = pack2(h2, h3);
                al[q]     = pack2(e0, e1);
                al[q + 2] = pack2(e2, e3);
            }
            uint32_t bv[8][2];
            #pragma unroll
            for (int np = 0; np < 4; np++)
                ldmVB(bv[2 * np], bv[2 * np + 1], s_vh, ks * 16, np * 16, lane);
            #pragma unroll
            for (int nt = 0; nt < 8; nt++) mma_f16(O[nt], ah, bv[nt]);
            #pragma unroll
            for (int nt = 0; nt < 8; nt++) mma_f16(O[nt], al, bv[nt]);
            #pragma unroll
            for (int np = 0; np < 4; np++)
                ldmVB(bv[2 * np], bv[2 * np + 1], s_vl, ks * 16, np * 16, lane);
            #pragma unroll
            for (int nt = 0; nt < 8; nt++) mma_f16(O[nt], ah, bv[nt]);
        }
    }

    l0 += __shfl_xor_sync(0xffffffffu, l0, 1);
    l0 += __shfl_xor_sync(0xffffffffu, l0, 2);
    l1 += __shfl_xor_sync(0xffffffffu, l1, 1);
    l1 += __shfl_xor_sync(0xffffffffu, l1, 2);
    float inv0 = 1.f / l0, inv1 = 1.f / l1;

    int r0 = tbase + w * 16 + (lane >> 2);
    #pragma unroll
    for (int nt = 0; nt < 8; nt++) {
        int col = h * HD_ + nt * 8 + (lane & 3) * 2;
        float v00 = O[nt][0] * inv0, v01 = O[nt][1] * inv0;
        float v10 = O[nt][2] * inv1, v11 = O[nt][3] * inv1;
        fp16 h0, e0, h1, e1;
        split1(v00, h0, e0); split1(v01, h1, e1);
        *(uint32_t*)(outh + (size_t)(b * T_ + r0) * D_ + col) = pack2(h0, h1);
        *(uint32_t*)(outl + (size_t)(b * T_ + r0) * D_ + col) = pack2(e0, e1);
        split1(v10, h0, e0); split1(v11, h1, e1);
        *(uint32_t*)(outh + (size_t)(b * T_ + r0 + 8) * D_ + col) = pack2(h0, h1);
        *(uint32_t*)(outl + (size_t)(b * T_ + r0 + 8) * D_ + col) = pack2(e0, e1);
    }
}

// ---------------- launch ----------------
extern "C" void kernel_launch(void* const* d_in, const int* in_sizes, int n_in,
                              void* d_out, int out_size) {
    const float* x  = (const float*)d_in[0];
    const float* Wi = (const float*)d_in[1];
    const float* bi = (const float*)d_in[2];
    const float* Wk = (const float*)d_in[3];
    const float* bk = (const float*)d_in[4];
    const float* Wq = (const float*)d_in[5];
    const float* bq = (const float*)d_in[6];
    const float* Wv = (const float*)d_in[7];
    const float* bv = (const float*)d_in[8];
    const float* Wo = (const float*)d_in[9];
    const float* bo = (const float*)d_in[10];
    float* out = (float*)d_out;

    fp16 *p_xh, *p_xl, *p_kqvh, *p_kqvl, *p_ah, *p_al;
    fp16 *p_wih, *p_wil, *p_wkh, *p_wkl, *p_wph, *p_wpl, *p_woh, *p_wol;
    float *p_bfused, *p_zero;
    cudaGetSymbolAddress((void**)&p_xh, g_xh);     cudaGetSymbolAddress((void**)&p_xl, g_xl);
    cudaGetSymbolAddress((void**)&p_kqvh, g_kqvh); cudaGetSymbolAddress((void**)&p_kqvl, g_kqvl);
    cudaGetSymbolAddress((void**)&p_ah, g_ah);     cudaGetSymbolAddress((void**)&p_al, g_al);
    cudaGetSymbolAddress((void**)&p_wih, g_wih);   cudaGetSymbolAddress((void**)&p_wil, g_wil);
    cudaGetSymbolAddress((void**)&p_wkh, g_wkh);   cudaGetSymbolAddress((void**)&p_wkl, g_wkl);
    cudaGetSymbolAddress((void**)&p_wph, g_wph);   cudaGetSymbolAddress((void**)&p_wpl, g_wpl);
    cudaGetSymbolAddress((void**)&p_woh, g_woh);   cudaGetSymbolAddress((void**)&p_wol, g_wol);
    cudaGetSymbolAddress((void**)&p_bfused, g_bfused);
    cudaGetSymbolAddress((void**)&p_zero, g_zero);

    static bool attr_set = false;
    if (!attr_set) {
        cudaFuncSetAttribute(gemm2_pre<1>, cudaFuncAttributeMaxDynamicSharedMemorySize, G2_SMEM);
        cudaFuncSetAttribute(gemm3_pre<0>, cudaFuncAttributeMaxDynamicSharedMemorySize, G3_SMEM);
        cudaFuncSetAttribute(gemm3_pre<1>, cudaFuncAttributeMaxDynamicSharedMemorySize, G3_SMEM);
        cudaFuncSetAttribute(attn_tc,      cudaFuncAttributeMaxDynamicSharedMemorySize, ATT_SMEM);
        attr_set = true;
    }

    // splits / repack
    split_kernel<<<(M_ * D_ / 4 + 255) / 256, 256>>>(x,  p_xh,  p_xl,  M_ * D_);
    split_kernel<<<(D_ * D_ / 4 + 255) / 256, 256>>>(Wi, p_wih, p_wil, D_ * D_);
    split_kernel<<<(D_ * D_ / 4 + 255) / 256, 256>>>(Wo, p_woh, p_wol, D_ * D_);
    repack_split_kernel<<<(3 * H_ * D_ * HD_ + 255) / 256, 256>>>(Wk, Wq, Wv, bk, bq, bv);
    bias_fuse_kernel<<<(N3 + 255) / 256, 256>>>(bi);

    {   // W' = Wi @ Wkqv  (3-combo, accuracy-critical, tiny) -> hi/lo
        dim3 grid(N3 / GBN, D_ / GBM);
        gemm3_pre<1><<<grid, GT, G3_SMEM>>>(D_, N3, D_, p_wih, p_wil, p_wkh, p_wkl,
                                            p_zero, nullptr, p_wph, p_wpl);
    }
    {   // kqv = x @ W' + b'  (2-combo, the big one) -> hi/lo
        dim3 grid(N3 / GBN, M_ / GBM);
        gemm2_pre<1><<<grid, GT, G2_SMEM>>>(M_, N3, D_, p_xh, p_xl, p_wph,
                                            p_bfused, nullptr, p_kqvh, p_kqvl);
    }
    {   // attention (3-combo) -> hi/lo
        dim3 grid(T_ / 128, H_, B_);
        attn_tc<<<grid, 256, ATT_SMEM>>>(p_kqvh, p_kqvl, p_ah, p_al);
    }
    {   // out = attn @ Wo + bo  (3-combo) -> fp32
        dim3 grid(D_ / GBN, M_ / GBM);
        gemm3_pre<0><<<grid, GT, G3_SMEM>>>(M_, D_, D_, p_ah, p_al, p_woh, p_wol,
                                            bo, out, nullptr, nullptr);
    }
}